// round 14
// baseline (speedup 1.0000x reference)
#include <cuda_runtime.h>
#include <math.h>

#define Bc 128
#define Nc 2048
#define Mc 128
#define NBLK 16            // streaming n-blocks per batch (128 rows each)
#define OUT_STRIDE (Mc + 2*Nc)   // 4224

// scratch (static device globals — no allocation allowed)
__device__ float g_exp [Bc * Nc];           // exp(scale*cos) per (b,n)
__device__ float g_part[Bc * NBLK * Mc];    // per-block column partial sums
__device__ float g_bsum[Bc * NBLK];         // per-block partial sum of exp
__device__ float g_bpow[Bc * NBLK];         // per-block partial sum of wprev^gamma
__device__ int   g_cnt [Bc];                // arrival counters (self-resetting)

// multi-value butterfly: 16 reductions (8 dots, 8 sqnorms) over 32 lanes.
__device__ __forceinline__ float butterfly_exp(
    float r[16], int lane, float scale, float* __restrict__ dst)
{
#pragma unroll
    for (int o = 16, nv = 16; o >= 2; o >>= 1, nv >>= 1) {
        const int half = nv >> 1;
#pragma unroll
        for (int j = 0; j < half; j++) {
            float send = (lane & o) ? r[j] : r[j + half];
            float recv = __shfl_xor_sync(0xFFFFFFFFu, send, o);
            r[j] = ((lane & o) ? r[j + half] : r[j]) + recv;
        }
    }
    r[0] += __shfl_xor_sync(0xFFFFFFFFu, r[0], 1);
    float other = __shfl_xor_sync(0xFFFFFFFFu, r[0], 16);

    float ex = 0.f;
    if ((lane < 16) && !(lane & 1)) {
        int i = lane >> 1;
        ex = __expf(scale * r[0] * rsqrtf(fmaxf(other, 1e-16f)));
        dst[i] = ex;
    }
    ex += __shfl_xor_sync(0xFFFFFFFFu, ex, 2);
    ex += __shfl_xor_sync(0xFFFFFFFFu, ex, 4);
    ex += __shfl_xor_sync(0xFFFFFFFFu, ex, 8);
    return ex;
}

// ---------------------------------------------------------------------------
// Finalizer (one block per batch): spin on counter, then pass2's work.
// __noinline__ so it cannot pollute the streaming path's register allocation.
// ---------------------------------------------------------------------------
__device__ __noinline__ void ntm_finalize(
    int b, const float* __restrict__ gt, const float* __restrict__ wprev,
    const float* __restrict__ e, const float* __restrict__ a,
    float* __restrict__ out)
{
    const int tid  = threadIdx.x;
    const int lane = tid & 31;

    if (tid == 0) {
        while (atomicAdd(&g_cnt[b], 0) < NBLK) __nanosleep(128);
        __threadfence();                    // acquire
    }
    __syncthreads();

    // warp-redundant scalar reduce over the 16 partials (L2-fresh)
    float es = __ldcg(&g_bsum[b * NBLK + (lane & 15)]);
    float pw = __ldcg(&g_bpow[b * NBLK + (lane & 15)]);
#pragma unroll
    for (int off = 8; off; off >>= 1) {
        es += __shfl_xor_sync(0xFFFFFFFFu, es, off);
        pw += __shfl_xor_sync(0xFFFFFFFFu, pw, off);
    }
    const float inv = 1.f / es;
    const float sB  = pw + 1e-6f;
    const float gv  = gt[b];
    const float og  = 1.f - gv;
    float* ob = out + (size_t)b * OUT_STRIDE;

    // w_t (broadcast scalar) and w_g: 2 float4 chunks per thread (512 total)
#pragma unroll
    for (int c = 0; c < 2; c++) {
        int n4 = tid * 2 + c;
        float4 ex4 = __ldcg(((const float4*)(g_exp + b * Nc)) + n4);
        float4 wp4 = ((const float4*)(wprev + b * Nc))[n4];
        ((float4*)(ob + Mc))[n4] = make_float4(sB, sB, sB, sB);
        float4 wg;
        wg.x = gv * ex4.x * inv + og * wp4.x;
        wg.y = gv * ex4.y * inv + og * wp4.y;
        wg.z = gv * ex4.z * inv + og * wp4.z;
        wg.w = gv * ex4.w * inv + og * wp4.w;
        ((float4*)(ob + Mc + Nc))[n4] = wg;
    }

    // r_t = sB * ((1 - sB*e) * colsum + N * sB * a)
    if (tid < Mc) {
        float Sm = 0.f;
#pragma unroll
        for (int j = 0; j < NBLK; j++)
            Sm += __ldcg(&g_part[((size_t)b * NBLK + j) * Mc + tid]);
        float ev = e[b * Mc + tid];
        float av = a[b * Mc + tid];
        ob[tid] = sB * ((1.f - sB * ev) * Sm + (float)Nc * sB * av);
    }

    __syncthreads();
    if (tid == 0) g_cnt[b] = 0;            // self-reset for graph replays
}

// ---------------------------------------------------------------------------
// Single fused launch. Blocks x<NBLK: R13 streaming path (unchanged).
// Block x==NBLK: finalizer.
// ---------------------------------------------------------------------------
__global__ void __launch_bounds__(256) ntm_all(
    const float* __restrict__ mem,   const float* __restrict__ k,
    const float* __restrict__ beta,  const float* __restrict__ wprev,
    const float* __restrict__ gamma, const float* __restrict__ gt,
    const float* __restrict__ e,     const float* __restrict__ a,
    float* __restrict__ out)
{
    const int b   = blockIdx.y;
    const int blk = blockIdx.x;

    if (blk == NBLK) {                      // finalizer block for this batch
        ntm_finalize(b, gt, wprev, e, a, out);
        return;
    }

    const int tid  = threadIdx.x;
    const int warp = tid >> 5;
    const int lane = tid & 31;

    // k row (with eps), 4 elements per lane
    float4 kv = ((const float4*)(k + b * Mc))[lane];
    kv.x += 1e-6f; kv.y += 1e-6f; kv.z += 1e-6f; kv.w += 1e-6f;

    // per-warp nk and scale (redundant across warps, no barrier)
    float kk = kv.x*kv.x + kv.y*kv.y + kv.z*kv.z + kv.w*kv.w;
#pragma unroll
    for (int off = 16; off; off >>= 1)
        kk += __shfl_xor_sync(0xFFFFFFFFu, kk, off);
    const float scale = beta[b] * rsqrtf(fmaxf(kk, 1e-16f));

    const int n0 = blk * 128 + warp * 16;
    const float4* mp = (const float4*)(mem + ((size_t)b * Nc + n0) * Mc);

    // prime the 8-deep rolling buffer with rows 0..7 (MLP=8)
    float4 cur[8];
#pragma unroll
    for (int i = 0; i < 8; i++) cur[i] = __ldcs(mp + i * 32 + lane);

    float cs0 = 0.f, cs1 = 0.f, cs2 = 0.f, cs3 = 0.f;

    float r1[16];
#pragma unroll
    for (int i = 0; i < 8; i++) {
        float4 t = cur[i];
        cur[i] = __ldcs(mp + (8 + i) * 32 + lane);   // refill keeps 8 in flight
        cs0 += t.x; cs1 += t.y; cs2 += t.z; cs3 += t.w;
        r1[i]     = t.x*kv.x + t.y*kv.y + t.z*kv.z + t.w*kv.w;
        r1[i + 8] = t.x*t.x  + t.y*t.y  + t.z*t.z  + t.w*t.w;
    }

    float ex = butterfly_exp(r1, lane, scale, g_exp + b * Nc + n0);

    float r2[16];
#pragma unroll
    for (int i = 0; i < 8; i++) {
        float4 t = cur[i];
        cs0 += t.x; cs1 += t.y; cs2 += t.z; cs3 += t.w;
        r2[i]     = t.x*kv.x + t.y*kv.y + t.z*kv.z + t.w*kv.w;
        r2[i + 8] = t.x*t.x  + t.y*t.y  + t.z*t.z  + t.w*t.w;
    }
    ex += butterfly_exp(r2, lane, scale, g_exp + b * Nc + n0 + 8);

    // wprev^gamma: 128 rows per block -> threads 0..127 load one row each
    float pw = 0.f;
    if (tid < 128)
        pw = __powf(wprev[b * Nc + blk * 128 + tid], gamma[b]);
#pragma unroll
    for (int off = 16; off; off >>= 1)
        pw += __shfl_xor_sync(0xFFFFFFFFu, pw, off);

    __shared__ float s_cs[8][Mc];
    __shared__ float s_exw[8];
    __shared__ float s_pww[8];
    {
        int m = lane * 4;
        s_cs[warp][m + 0] = cs0;
        s_cs[warp][m + 1] = cs1;
        s_cs[warp][m + 2] = cs2;
        s_cs[warp][m + 3] = cs3;
        if (lane == 0) { s_exw[warp] = ex; s_pww[warp] = pw; }
    }
    __syncthreads();

    if (tid < Mc) {
        float s = 0.f;
#pragma unroll
        for (int wi = 0; wi < 8; wi++) s += s_cs[wi][tid];
        g_part[((size_t)b * NBLK + blk) * Mc + tid] = s;
    }
    if (tid == 0) {
        float se = 0.f, sp = 0.f;
#pragma unroll
        for (int wi = 0; wi < 8; wi++) { se += s_exw[wi]; sp += s_pww[wi]; }
        g_bsum[b * NBLK + blk] = se;
        g_bpow[b * NBLK + blk] = sp;
    }

    // publish: all writes visible, then count arrival
    __threadfence();
    __syncthreads();
    if (tid == 0) atomicAdd(&g_cnt[b], 1);
}

extern "C" void kernel_launch(void* const* d_in, const int* in_sizes, int n_in,
                              void* d_out, int out_size)
{
    const float* mem   = (const float*)d_in[0];
    const float* k     = (const float*)d_in[1];
    const float* beta  = (const float*)d_in[2];
    const float* gt    = (const float*)d_in[3];
    const float* wprev = (const float*)d_in[4];
    // d_in[5] = s_t (unused by the reference's live outputs)
    const float* gamma = (const float*)d_in[6];
    const float* e     = (const float*)d_in[7];
    const float* a     = (const float*)d_in[8];
    float* out = (float*)d_out;

    ntm_all<<<dim3(NBLK + 1, Bc), 256>>>(mem, k, beta, wprev, gamma,
                                         gt, e, a, out);
}

// round 15
// speedup vs baseline: 1.0077x; 1.0077x over previous
#include <cuda_runtime.h>
#include <math.h>

#define Bc 128
#define Nc 2048
#define Mc 128
#define NBLK 16              // n-tiles per batch (128 rows each)
#define NTILES (Bc * NBLK)   // 2048 total tiles
#define PERS_GRID 740        // one full wave: 148 SMs x 5 CTAs
#define OUT_STRIDE (Mc + 2*Nc)   // 4224

// scratch (static device globals — no allocation allowed)
__device__ float g_exp [Bc * Nc];           // exp(scale*cos) per (b,n)
__device__ float g_part[Bc * NBLK * Mc];    // per-tile column partial sums
__device__ float g_bsum[Bc * NBLK];         // per-tile partial sum of exp
__device__ float g_bpow[Bc * NBLK];         // per-tile partial sum of wprev^gamma
__device__ int   g_tile = PERS_GRID;        // work-steal ticket (reset by pass2)

// multi-value butterfly: 16 reductions (8 dots, 8 sqnorms) over 32 lanes.
__device__ __forceinline__ float butterfly_exp(
    float r[16], int lane, float scale, float* __restrict__ dst)
{
#pragma unroll
    for (int o = 16, nv = 16; o >= 2; o >>= 1, nv >>= 1) {
        const int half = nv >> 1;
#pragma unroll
        for (int j = 0; j < half; j++) {
            float send = (lane & o) ? r[j] : r[j + half];
            float recv = __shfl_xor_sync(0xFFFFFFFFu, send, o);
            r[j] = ((lane & o) ? r[j + half] : r[j]) + recv;
        }
    }
    r[0] += __shfl_xor_sync(0xFFFFFFFFu, r[0], 1);
    float other = __shfl_xor_sync(0xFFFFFFFFu, r[0], 16);

    float ex = 0.f;
    if ((lane < 16) && !(lane & 1)) {
        int i = lane >> 1;
        ex = __expf(scale * r[0] * rsqrtf(fmaxf(other, 1e-16f)));
        dst[i] = ex;
    }
    ex += __shfl_xor_sync(0xFFFFFFFFu, ex, 2);
    ex += __shfl_xor_sync(0xFFFFFFFFu, ex, 4);
    ex += __shfl_xor_sync(0xFFFFFFFFu, ex, 8);
    return ex;
}

// ---------------------------------------------------------------------------
// Pass 1: PERSISTENT streaming sweep. 740 blocks (one wave), work-stealing
// over 2048 tiles. Per tile: identical to the proven R13 streaming body.
// ---------------------------------------------------------------------------
__global__ void __launch_bounds__(256) ntm_pass1(
    const float* __restrict__ mem,   const float* __restrict__ k,
    const float* __restrict__ beta,  const float* __restrict__ wprev,
    const float* __restrict__ gamma)
{
    const int tid  = threadIdx.x;
    const int warp = tid >> 5;
    const int lane = tid & 31;

    __shared__ float s_cs[8][Mc];
    __shared__ float s_exw[8];
    __shared__ float s_pww[8];
    __shared__ int   s_next;

    int tile = blockIdx.x;
    while (tile < NTILES) {
        const int b   = tile >> 4;          // tile / NBLK
        const int blk = tile & 15;          // tile % NBLK

        // k row (with eps), 4 elements per lane (L2-warm after first touch)
        float4 kv = ((const float4*)(k + b * Mc))[lane];
        kv.x += 1e-6f; kv.y += 1e-6f; kv.z += 1e-6f; kv.w += 1e-6f;

        float kk = kv.x*kv.x + kv.y*kv.y + kv.z*kv.z + kv.w*kv.w;
#pragma unroll
        for (int off = 16; off; off >>= 1)
            kk += __shfl_xor_sync(0xFFFFFFFFu, kk, off);
        const float scale = beta[b] * rsqrtf(fmaxf(kk, 1e-16f));

        const int n0 = blk * 128 + warp * 16;
        const float4* mp = (const float4*)(mem + ((size_t)b * Nc + n0) * Mc);

        // prime the 8-deep rolling buffer with rows 0..7 (MLP=8)
        float4 cur[8];
#pragma unroll
        for (int i = 0; i < 8; i++) cur[i] = __ldcs(mp + i * 32 + lane);

        float cs0 = 0.f, cs1 = 0.f, cs2 = 0.f, cs3 = 0.f;

        float r1[16];
#pragma unroll
        for (int i = 0; i < 8; i++) {
            float4 t = cur[i];
            cur[i] = __ldcs(mp + (8 + i) * 32 + lane);   // refill, keep 8 in flight
            cs0 += t.x; cs1 += t.y; cs2 += t.z; cs3 += t.w;
            r1[i]     = t.x*kv.x + t.y*kv.y + t.z*kv.z + t.w*kv.w;
            r1[i + 8] = t.x*t.x  + t.y*t.y  + t.z*t.z  + t.w*t.w;
        }

        float ex = butterfly_exp(r1, lane, scale, g_exp + b * Nc + n0);

        float r2[16];
#pragma unroll
        for (int i = 0; i < 8; i++) {
            float4 t = cur[i];
            cs0 += t.x; cs1 += t.y; cs2 += t.z; cs3 += t.w;
            r2[i]     = t.x*kv.x + t.y*kv.y + t.z*kv.z + t.w*kv.w;
            r2[i + 8] = t.x*t.x  + t.y*t.y  + t.z*t.z  + t.w*t.w;
        }
        ex += butterfly_exp(r2, lane, scale, g_exp + b * Nc + n0 + 8);

        // wprev^gamma: 128 rows per tile -> threads 0..127 load one row each
        float pw = 0.f;
        if (tid < 128)
            pw = __powf(wprev[b * Nc + blk * 128 + tid], gamma[b]);
#pragma unroll
        for (int off = 16; off; off >>= 1)
            pw += __shfl_xor_sync(0xFFFFFFFFu, pw, off);

        {
            int m = lane * 4;
            s_cs[warp][m + 0] = cs0;
            s_cs[warp][m + 1] = cs1;
            s_cs[warp][m + 2] = cs2;
            s_cs[warp][m + 3] = cs3;
            if (lane == 0) { s_exw[warp] = ex; s_pww[warp] = pw; }
        }
        __syncthreads();

        if (tid < Mc) {
            float s = 0.f;
#pragma unroll
            for (int wi = 0; wi < 8; wi++) s += s_cs[wi][tid];
            g_part[((size_t)b * NBLK + blk) * Mc + tid] = s;
        }
        if (tid == 0) {
            float se = 0.f, sp = 0.f;
#pragma unroll
            for (int wi = 0; wi < 8; wi++) { se += s_exw[wi]; sp += s_pww[wi]; }
            g_bsum[b * NBLK + blk] = se;
            g_bpow[b * NBLK + blk] = sp;
            s_next = atomicAdd(&g_tile, 1);     // steal next tile
        }
        __syncthreads();                        // s_next ready + smem reusable
        tile = s_next;
    }
}

// ---------------------------------------------------------------------------
// Pass 2 (R13 config, measured 5.5us): grid (2, B) x 512. Warps 0-7: w_g;
// warps 8-15: w_t broadcast store; split 0 / tid<128: r_t. Barrier-free
// warp-redundant scalar reduce. Also resets the work-steal ticket.
// ---------------------------------------------------------------------------
__global__ void __launch_bounds__(512) ntm_pass2(
    const float* __restrict__ gt,   const float* __restrict__ wprev,
    const float* __restrict__ e,    const float* __restrict__ a,
    float* __restrict__ out)
{
    const int b    = blockIdx.y;
    const int s    = blockIdx.x;          // 0 or 1 (N-half)
    const int tid  = threadIdx.x;
    const int lane = tid & 31;
    const int n4   = s * 256 + (tid & 255);   // float4 index into [Nc]

    // reset pass1's ticket for the next graph replay (stream-ordered after pass1)
    if (b == 0 && s == 0 && tid == 0) g_tile = PERS_GRID;

    const float gv = gt[b];

    float4 ex4, wp4;
    if (tid < 256) {
        ex4 = ((const float4*)(g_exp  + b * Nc))[n4];
        wp4 = ((const float4*)(wprev + b * Nc))[n4];
    }
    float evv = 0.f, avv = 0.f, Sm = 0.f;
    if (s == 0 && tid < Mc) {
        evv = e[b * Mc + tid];
        avv = a[b * Mc + tid];
#pragma unroll
        for (int j = 0; j < NBLK; j++)
            Sm += g_part[((size_t)b * NBLK + j) * Mc + tid];
    }

    // warp-redundant scalar reduce (no barrier, no smem)
    float es = g_bsum[b * NBLK + (lane & 15)];
    float pw = g_bpow[b * NBLK + (lane & 15)];
#pragma unroll
    for (int off = 8; off; off >>= 1) {
        es += __shfl_xor_sync(0xFFFFFFFFu, es, off);
        pw += __shfl_xor_sync(0xFFFFFFFFu, pw, off);
    }
    const float inv = 1.f / es;
    const float sB  = pw + 1e-6f;
    const float og  = 1.f - gv;
    float* ob = out + (size_t)b * OUT_STRIDE;

    if (tid < 256) {
        float4 wg;
        wg.x = gv * ex4.x * inv + og * wp4.x;
        wg.y = gv * ex4.y * inv + og * wp4.y;
        wg.z = gv * ex4.z * inv + og * wp4.z;
        wg.w = gv * ex4.w * inv + og * wp4.w;
        ((float4*)(ob + Mc + Nc))[n4] = wg;
    } else {
        ((float4*)(ob + Mc))[n4] = make_float4(sB, sB, sB, sB);
    }

    if (s == 0 && tid < Mc) {
        // r_t = sB * ((1 - sB*e) * colsum + N * sB * a)
        ob[tid] = sB * ((1.f - sB * evv) * Sm + (float)Nc * sB * avv);
    }
}

extern "C" void kernel_launch(void* const* d_in, const int* in_sizes, int n_in,
                              void* d_out, int out_size)
{
    const float* mem   = (const float*)d_in[0];
    const float* k     = (const float*)d_in[1];
    const float* beta  = (const float*)d_in[2];
    const float* gt    = (const float*)d_in[3];
    const float* wprev = (const float*)d_in[4];
    // d_in[5] = s_t (unused by the reference's live outputs)
    const float* gamma = (const float*)d_in[6];
    const float* e     = (const float*)d_in[7];
    const float* a     = (const float*)d_in[8];
    float* out = (float*)d_out;

    ntm_pass1<<<PERS_GRID, 256>>>(mem, k, beta, wprev, gamma);
    ntm_pass2<<<dim3(2, Bc), 512>>>(gt, wprev, e, a, out);
}

// round 16
// speedup vs baseline: 1.1504x; 1.1416x over previous
#include <cuda_runtime.h>
#include <math.h>

#define Bc 128
#define Nc 2048
#define Mc 128
#define NPART 8              // partials per batch (one per block; 256 rows each)
#define OUT_STRIDE (Mc + 2*Nc)   // 4224

// scratch (static device globals — no allocation allowed)
__device__ float g_exp [Bc * Nc];            // exp(scale*cos) per (b,n)
__device__ float g_part[Bc * NPART * Mc];    // per-block column partial sums
__device__ float g_bsum[Bc * NPART];         // per-block partial sum of exp
__device__ float g_bpow[Bc * NPART];         // per-block partial sum of wprev^gamma

// multi-value butterfly: 16 reductions (8 dots, 8 sqnorms) over 32 lanes.
__device__ __forceinline__ float butterfly_exp(
    float r[16], int lane, float scale, float* __restrict__ dst)
{
#pragma unroll
    for (int o = 16, nv = 16; o >= 2; o >>= 1, nv >>= 1) {
        const int half = nv >> 1;
#pragma unroll
        for (int j = 0; j < half; j++) {
            float send = (lane & o) ? r[j] : r[j + half];
            float recv = __shfl_xor_sync(0xFFFFFFFFu, send, o);
            r[j] = ((lane & o) ? r[j + half] : r[j]) + recv;
        }
    }
    r[0] += __shfl_xor_sync(0xFFFFFFFFu, r[0], 1);
    float other = __shfl_xor_sync(0xFFFFFFFFu, r[0], 16);

    float ex = 0.f;
    if ((lane < 16) && !(lane & 1)) {
        int i = lane >> 1;
        ex = __expf(scale * r[0] * rsqrtf(fmaxf(other, 1e-16f)));
        dst[i] = ex;
    }
    ex += __shfl_xor_sync(0xFFFFFFFFu, ex, 2);
    ex += __shfl_xor_sync(0xFFFFFFFFu, ex, 4);
    ex += __shfl_xor_sync(0xFFFFFFFFu, ex, 8);
    return ex;
}

// ---------------------------------------------------------------------------
// Pass 1: grid (8, B) x 256. Each block: 2 tiles (blk, blk+8) of one batch =
// 256 rows; each warp 32 rows in 4 pipelined consume/refill groups through an
// 8-deep rolling buffer — loads stay in flight across 3 of 4 butterfly phases.
// One block tail per 256 rows (was per 128).
// ---------------------------------------------------------------------------
__global__ void __launch_bounds__(256) ntm_pass1(
    const float* __restrict__ mem,   const float* __restrict__ k,
    const float* __restrict__ beta,  const float* __restrict__ wprev,
    const float* __restrict__ gamma)
{
    const int b    = blockIdx.y;
    const int blk  = blockIdx.x;          // 0..7
    const int tid  = threadIdx.x;
    const int warp = tid >> 5;
    const int lane = tid & 31;

    // k row (with eps), 4 elements per lane
    float4 kv = ((const float4*)(k + b * Mc))[lane];
    kv.x += 1e-6f; kv.y += 1e-6f; kv.z += 1e-6f; kv.w += 1e-6f;

    // per-warp nk and scale (redundant across warps, no barrier)
    float kk = kv.x*kv.x + kv.y*kv.y + kv.z*kv.z + kv.w*kv.w;
#pragma unroll
    for (int off = 16; off; off >>= 1)
        kk += __shfl_xor_sync(0xFFFFFFFFu, kk, off);
    const float scale = beta[b] * rsqrtf(fmaxf(kk, 1e-16f));

    const int nA = blk * 128 + warp * 16;          // tile A rows
    const int nB = (blk + 8) * 128 + warp * 16;    // tile B rows (same batch)
    const float4* mpA = (const float4*)(mem + ((size_t)b * Nc + nA) * Mc);
    const float4* mpB = (const float4*)(mem + ((size_t)b * Nc + nB) * Mc);

    // prime the 8-deep rolling buffer with A rows 0..7 (MLP=8)
    float4 cur[8];
#pragma unroll
    for (int i = 0; i < 8; i++) cur[i] = __ldcs(mpA + i * 32 + lane);

    float cs0 = 0.f, cs1 = 0.f, cs2 = 0.f, cs3 = 0.f;
    float r[16];
    float ex;

    // group 1: consume A0-7, refill A8-15
#pragma unroll
    for (int i = 0; i < 8; i++) {
        float4 t = cur[i];
        cur[i] = __ldcs(mpA + (8 + i) * 32 + lane);
        cs0 += t.x; cs1 += t.y; cs2 += t.z; cs3 += t.w;
        r[i]     = t.x*kv.x + t.y*kv.y + t.z*kv.z + t.w*kv.w;
        r[i + 8] = t.x*t.x  + t.y*t.y  + t.z*t.z  + t.w*t.w;
    }
    ex = butterfly_exp(r, lane, scale, g_exp + b * Nc + nA);

    // group 2: consume A8-15, refill B0-7
#pragma unroll
    for (int i = 0; i < 8; i++) {
        float4 t = cur[i];
        cur[i] = __ldcs(mpB + i * 32 + lane);
        cs0 += t.x; cs1 += t.y; cs2 += t.z; cs3 += t.w;
        r[i]     = t.x*kv.x + t.y*kv.y + t.z*kv.z + t.w*kv.w;
        r[i + 8] = t.x*t.x  + t.y*t.y  + t.z*t.z  + t.w*t.w;
    }
    ex += butterfly_exp(r, lane, scale, g_exp + b * Nc + nA + 8);

    // group 3: consume B0-7, refill B8-15
#pragma unroll
    for (int i = 0; i < 8; i++) {
        float4 t = cur[i];
        cur[i] = __ldcs(mpB + (8 + i) * 32 + lane);
        cs0 += t.x; cs1 += t.y; cs2 += t.z; cs3 += t.w;
        r[i]     = t.x*kv.x + t.y*kv.y + t.z*kv.z + t.w*kv.w;
        r[i + 8] = t.x*t.x  + t.y*t.y  + t.z*t.z  + t.w*t.w;
    }
    ex += butterfly_exp(r, lane, scale, g_exp + b * Nc + nB);

    // group 4: consume B8-15
#pragma unroll
    for (int i = 0; i < 8; i++) {
        float4 t = cur[i];
        cs0 += t.x; cs1 += t.y; cs2 += t.z; cs3 += t.w;
        r[i]     = t.x*kv.x + t.y*kv.y + t.z*kv.z + t.w*kv.w;
        r[i + 8] = t.x*t.x  + t.y*t.y  + t.z*t.z  + t.w*t.w;
    }
    ex += butterfly_exp(r, lane, scale, g_exp + b * Nc + nB + 8);

    // wprev^gamma: 256 rows per block -> every thread loads one row
    const int prow = (tid < 128) ? (blk * 128 + tid)
                                 : ((blk + 8) * 128 + (tid - 128));
    float pw = __powf(wprev[b * Nc + prow], gamma[b]);
#pragma unroll
    for (int off = 16; off; off >>= 1)
        pw += __shfl_xor_sync(0xFFFFFFFFu, pw, off);

    __shared__ float s_cs[8][Mc];
    __shared__ float s_exw[8];
    __shared__ float s_pww[8];
    {
        int m = lane * 4;
        s_cs[warp][m + 0] = cs0;
        s_cs[warp][m + 1] = cs1;
        s_cs[warp][m + 2] = cs2;
        s_cs[warp][m + 3] = cs3;
        if (lane == 0) { s_exw[warp] = ex; s_pww[warp] = pw; }
    }
    __syncthreads();

    if (tid < Mc) {
        float s = 0.f;
#pragma unroll
        for (int wi = 0; wi < 8; wi++) s += s_cs[wi][tid];
        g_part[((size_t)b * NPART + blk) * Mc + tid] = s;
    }
    if (tid == 0) {
        float se = 0.f, sp = 0.f;
#pragma unroll
        for (int wi = 0; wi < 8; wi++) { se += s_exw[wi]; sp += s_pww[wi]; }
        g_bsum[b * NPART + blk] = se;
        g_bpow[b * NPART + blk] = sp;
    }
}

// ---------------------------------------------------------------------------
// Pass 2 (R13 shape): grid (2, B) x 512. Warps 0-7: w_g; warps 8-15: w_t
// broadcast store; split 0 / tid<128: r_t. Barrier-free warp-redundant
// scalar reduce over the 8 partials.
// ---------------------------------------------------------------------------
__global__ void __launch_bounds__(512) ntm_pass2(
    const float* __restrict__ gt,   const float* __restrict__ wprev,
    const float* __restrict__ e,    const float* __restrict__ a,
    float* __restrict__ out)
{
    const int b    = blockIdx.y;
    const int s    = blockIdx.x;          // 0 or 1 (N-half)
    const int tid  = threadIdx.x;
    const int lane = tid & 31;
    const int n4   = s * 256 + (tid & 255);   // float4 index into [Nc]

    const float gv = gt[b];

    // ---- prefetch (only the threads that need them issue loads) ----
    float4 ex4, wp4;
    if (tid < 256) {
        ex4 = ((const float4*)(g_exp  + b * Nc))[n4];
        wp4 = ((const float4*)(wprev + b * Nc))[n4];
    }
    float evv = 0.f, avv = 0.f, Sm = 0.f;
    if (s == 0 && tid < Mc) {
        evv = e[b * Mc + tid];
        avv = a[b * Mc + tid];
#pragma unroll
        for (int j = 0; j < NPART; j++)
            Sm += g_part[((size_t)b * NPART + j) * Mc + tid];
    }

    // ---- warp-redundant scalar reduce over 8 partials (no barrier) ----
    float es = g_bsum[b * NPART + (lane & 7)];
    float pw = g_bpow[b * NPART + (lane & 7)];
#pragma unroll
    for (int off = 4; off; off >>= 1) {
        es += __shfl_xor_sync(0xFFFFFFFFu, es, off);
        pw += __shfl_xor_sync(0xFFFFFFFFu, pw, off);
    }
    const float inv = 1.f / es;
    const float sB  = pw + 1e-6f;
    const float og  = 1.f - gv;
    float* ob = out + (size_t)b * OUT_STRIDE;

    if (tid < 256) {
        // w_g half
        float4 wg;
        wg.x = gv * ex4.x * inv + og * wp4.x;
        wg.y = gv * ex4.y * inv + og * wp4.y;
        wg.z = gv * ex4.z * inv + og * wp4.z;
        wg.w = gv * ex4.w * inv + og * wp4.w;
        ((float4*)(ob + Mc + Nc))[n4] = wg;
    } else {
        // w_t half: pure broadcast store
        ((float4*)(ob + Mc))[n4] = make_float4(sB, sB, sB, sB);
    }

    if (s == 0 && tid < Mc) {
        // r_t = sB * ((1 - sB*e) * colsum + N * sB * a)
        ob[tid] = sB * ((1.f - sB * evv) * Sm + (float)Nc * sB * avv);
    }
}

extern "C" void kernel_launch(void* const* d_in, const int* in_sizes, int n_in,
                              void* d_out, int out_size)
{
    const float* mem   = (const float*)d_in[0];
    const float* k     = (const float*)d_in[1];
    const float* beta  = (const float*)d_in[2];
    const float* gt    = (const float*)d_in[3];
    const float* wprev = (const float*)d_in[4];
    // d_in[5] = s_t (unused by the reference's live outputs)
    const float* gamma = (const float*)d_in[6];
    const float* e     = (const float*)d_in[7];
    const float* a     = (const float*)d_in[8];
    float* out = (float*)d_out;

    ntm_pass1<<<dim3(NPART, Bc), 256>>>(mem, k, beta, wprev, gamma);
    ntm_pass2<<<dim3(2, Bc), 512>>>(gt, wprev, e, a, out);
}

// round 17
// speedup vs baseline: 1.2373x; 1.0756x over previous
#include <cuda_runtime.h>
#include <math.h>

#define Bc 128
#define Nc 2048
#define Mc 128
#define NPART 4              // partials per batch (one per block; 512 rows each)
#define OUT_STRIDE (Mc + 2*Nc)   // 4224

// scratch (static device globals — no allocation allowed)
__device__ float g_exp [Bc * Nc];            // exp(scale*cos) per (b,n)
__device__ float g_part[Bc * NPART * Mc];    // per-block column partial sums
__device__ float g_bsum[Bc * NPART];         // per-block partial sum of exp
__device__ float g_bpow[Bc * NPART];         // per-block partial sum of wprev^gamma

// multi-value butterfly: 16 reductions (8 dots, 8 sqnorms) over 32 lanes.
__device__ __forceinline__ float butterfly_exp(
    float r[16], int lane, float scale, float* __restrict__ dst)
{
#pragma unroll
    for (int o = 16, nv = 16; o >= 2; o >>= 1, nv >>= 1) {
        const int half = nv >> 1;
#pragma unroll
        for (int j = 0; j < half; j++) {
            float send = (lane & o) ? r[j] : r[j + half];
            float recv = __shfl_xor_sync(0xFFFFFFFFu, send, o);
            r[j] = ((lane & o) ? r[j + half] : r[j]) + recv;
        }
    }
    r[0] += __shfl_xor_sync(0xFFFFFFFFu, r[0], 1);
    float other = __shfl_xor_sync(0xFFFFFFFFu, r[0], 16);

    float ex = 0.f;
    if ((lane < 16) && !(lane & 1)) {
        int i = lane >> 1;
        ex = __expf(scale * r[0] * rsqrtf(fmaxf(other, 1e-16f)));
        dst[i] = ex;
    }
    ex += __shfl_xor_sync(0xFFFFFFFFu, ex, 2);
    ex += __shfl_xor_sync(0xFFFFFFFFu, ex, 4);
    ex += __shfl_xor_sync(0xFFFFFFFFu, ex, 8);
    return ex;
}

// ---------------------------------------------------------------------------
// Pass 1: grid (4, B) x 256. Each block: 4 tiles (blk, blk+4, blk+8, blk+12)
// of one batch = 512 rows. Each warp: 64 rows in 8 pipelined consume/refill
// groups through an 8-deep rolling buffer — loads in flight across 7 of 8
// butterfly phases. One block tail per 512 rows. Single wave (512 blocks).
// ---------------------------------------------------------------------------
__global__ void __launch_bounds__(256) ntm_pass1(
    const float* __restrict__ mem,   const float* __restrict__ k,
    const float* __restrict__ beta,  const float* __restrict__ wprev,
    const float* __restrict__ gamma)
{
    const int b    = blockIdx.y;
    const int blk  = blockIdx.x;          // 0..3
    const int tid  = threadIdx.x;
    const int warp = tid >> 5;
    const int lane = tid & 31;

    // k row (with eps), 4 elements per lane
    float4 kv = ((const float4*)(k + b * Mc))[lane];
    kv.x += 1e-6f; kv.y += 1e-6f; kv.z += 1e-6f; kv.w += 1e-6f;

    // per-warp nk and scale (redundant across warps, no barrier)
    float kk = kv.x*kv.x + kv.y*kv.y + kv.z*kv.z + kv.w*kv.w;
#pragma unroll
    for (int off = 16; off; off >>= 1)
        kk += __shfl_xor_sync(0xFFFFFFFFu, kk, off);
    const float scale = beta[b] * rsqrtf(fmaxf(kk, 1e-16f));

    // group g (0..7): tile t = g>>1 at rows (blk + 4t)*128, half h = g&1.
    // row base of group g: (blk + 4*(g>>1))*128 + warp*16 + (g&1)*8
    const float4* base = (const float4*)(mem + (size_t)b * Nc * Mc);
    int n_g[8];
#pragma unroll
    for (int g = 0; g < 8; g++)
        n_g[g] = (blk + 4 * (g >> 1)) * 128 + warp * 16 + (g & 1) * 8;

    // prime the 8-deep rolling buffer with group 0 (MLP=8)
    float4 cur[8];
#pragma unroll
    for (int i = 0; i < 8; i++)
        cur[i] = __ldcs(base + (size_t)(n_g[0] + i) * 32 + lane);

    float cs0 = 0.f, cs1 = 0.f, cs2 = 0.f, cs3 = 0.f;
    float ex = 0.f;
    float r[16];

#pragma unroll
    for (int g = 0; g < 8; g++) {
#pragma unroll
        for (int i = 0; i < 8; i++) {
            float4 t = cur[i];
            if (g < 7)   // refill with group g+1 while consuming group g
                cur[i] = __ldcs(base + (size_t)(n_g[g + 1] + i) * 32 + lane);
            cs0 += t.x; cs1 += t.y; cs2 += t.z; cs3 += t.w;
            r[i]     = t.x*kv.x + t.y*kv.y + t.z*kv.z + t.w*kv.w;
            r[i + 8] = t.x*t.x  + t.y*t.y  + t.z*t.z  + t.w*t.w;
        }
        ex += butterfly_exp(r, lane, scale, g_exp + b * Nc + n_g[g]);
    }

    // wprev^gamma: 512 rows per block, 256 threads -> 2 rows per thread
    const float gam = gamma[b];
    const int t1 = tid >> 7;                   // 0 or 1
    const int lr = tid & 127;
    float pw = __powf(wprev[b * Nc + (blk + 4 * t1)       * 128 + lr], gam)
             + __powf(wprev[b * Nc + (blk + 4 * (t1 + 2)) * 128 + lr], gam);
#pragma unroll
    for (int off = 16; off; off >>= 1)
        pw += __shfl_xor_sync(0xFFFFFFFFu, pw, off);

    __shared__ float s_cs[8][Mc];
    __shared__ float s_exw[8];
    __shared__ float s_pww[8];
    {
        int m = lane * 4;
        s_cs[warp][m + 0] = cs0;
        s_cs[warp][m + 1] = cs1;
        s_cs[warp][m + 2] = cs2;
        s_cs[warp][m + 3] = cs3;
        if (lane == 0) { s_exw[warp] = ex; s_pww[warp] = pw; }
    }
    __syncthreads();

    if (tid < Mc) {
        float s = 0.f;
#pragma unroll
        for (int wi = 0; wi < 8; wi++) s += s_cs[wi][tid];
        g_part[((size_t)b * NPART + blk) * Mc + tid] = s;
    }
    if (tid == 0) {
        float se = 0.f, sp = 0.f;
#pragma unroll
        for (int wi = 0; wi < 8; wi++) { se += s_exw[wi]; sp += s_pww[wi]; }
        g_bsum[b * NPART + blk] = se;
        g_bpow[b * NPART + blk] = sp;
    }
}

// ---------------------------------------------------------------------------
// Pass 2 (R13 shape): grid (2, B) x 512. Warps 0-7: w_g; warps 8-15: w_t
// broadcast store; split 0 / tid<128: r_t. Barrier-free warp-redundant
// scalar reduce over the 4 partials.
// ---------------------------------------------------------------------------
__global__ void __launch_bounds__(512) ntm_pass2(
    const float* __restrict__ gt,   const float* __restrict__ wprev,
    const float* __restrict__ e,    const float* __restrict__ a,
    float* __restrict__ out)
{
    const int b    = blockIdx.y;
    const int s    = blockIdx.x;          // 0 or 1 (N-half)
    const int tid  = threadIdx.x;
    const int lane = tid & 31;
    const int n4   = s * 256 + (tid & 255);   // float4 index into [Nc]

    const float gv = gt[b];

    // ---- prefetch (only the threads that need them issue loads) ----
    float4 ex4, wp4;
    if (tid < 256) {
        ex4 = ((const float4*)(g_exp  + b * Nc))[n4];
        wp4 = ((const float4*)(wprev + b * Nc))[n4];
    }
    float evv = 0.f, avv = 0.f, Sm = 0.f;
    if (s == 0 && tid < Mc) {
        evv = e[b * Mc + tid];
        avv = a[b * Mc + tid];
#pragma unroll
        for (int j = 0; j < NPART; j++)
            Sm += g_part[((size_t)b * NPART + j) * Mc + tid];
    }

    // ---- warp-redundant scalar reduce over 4 partials (no barrier) ----
    float es = g_bsum[b * NPART + (lane & 3)];
    float pw = g_bpow[b * NPART + (lane & 3)];
#pragma unroll
    for (int off = 2; off; off >>= 1) {
        es += __shfl_xor_sync(0xFFFFFFFFu, es, off);
        pw += __shfl_xor_sync(0xFFFFFFFFu, pw, off);
    }
    const float inv = 1.f / es;
    const float sB  = pw + 1e-6f;
    const float og  = 1.f - gv;
    float* ob = out + (size_t)b * OUT_STRIDE;

    if (tid < 256) {
        // w_g half
        float4 wg;
        wg.x = gv * ex4.x * inv + og * wp4.x;
        wg.y = gv * ex4.y * inv + og * wp4.y;
        wg.z = gv * ex4.z * inv + og * wp4.z;
        wg.w = gv * ex4.w * inv + og * wp4.w;
        ((float4*)(ob + Mc + Nc))[n4] = wg;
    } else {
        // w_t half: pure broadcast store
        ((float4*)(ob + Mc))[n4] = make_float4(sB, sB, sB, sB);
    }

    if (s == 0 && tid < Mc) {
        // r_t = sB * ((1 - sB*e) * colsum + N * sB * a)
        ob[tid] = sB * ((1.f - sB * evv) * Sm + (float)Nc * sB * avv);
    }
}

extern "C" void kernel_launch(void* const* d_in, const int* in_sizes, int n_in,
                              void* d_out, int out_size)
{
    const float* mem   = (const float*)d_in[0];
    const float* k     = (const float*)d_in[1];
    const float* beta  = (const float*)d_in[2];
    const float* gt    = (const float*)d_in[3];
    const float* wprev = (const float*)d_in[4];
    // d_in[5] = s_t (unused by the reference's live outputs)
    const float* gamma = (const float*)d_in[6];
    const float* e     = (const float*)d_in[7];
    const float* a     = (const float*)d_in[8];
    float* out = (float*)d_out;

    ntm_pass1<<<dim3(NPART, Bc), 256>>>(mem, k, beta, wprev, gamma);
    ntm_pass2<<<dim3(2, Bc), 512>>>(gt, wprev, e, a, out);
}